// round 7
// baseline (speedup 1.0000x reference)
#include <cuda_runtime.h>
#include <cuda_bf16.h>

#define N_TOTAL   16384
#define M_ROWS    4096
#define DIM       256
#define K1_BLOCKS 512          // colsum blocks (one full-occupancy wave)
#define R1_BLOCKS 32           // reduce1 blocks

// Scratch (no allocation allowed)
__device__ float g_part [K1_BLOCKS * DIM];  // colsum per-block partials
__device__ float g_part2[R1_BLOCKS * DIM];  // stage-2 partials
__device__ float g_ksum[DIM];
__device__ float g_v[DIM];
__device__ float g_c;

// ---------------------------------------------------------------------------
// k1: column partial sums of combine_new = [mashup ; new_api]
// 512 blocks x 512 threads = 262144 threads; 16384 rows x 64 float4-cols
// = 1048576 float4 loads -> exactly 4 per thread, no predication.
// Row map: r = bid + 512*(sub + 8*m), sub = t>>6 in 0..7, m in 0..3.
// Warp-coalesced (sub constant within a warp, c4 = t&63 contiguous).
// Single wave at 4 blocks/SM -> ~86% occupancy, no tail.
// ---------------------------------------------------------------------------
__global__ void __launch_bounds__(512, 4)
colsum_kernel(const float* __restrict__ mashup,
              const float* __restrict__ new_api) {
    const int t   = threadIdx.x;
    const int c4  = t & 63;
    const int sub = t >> 6;                 // 0..7
    const int bid = blockIdx.x;

    float4 acc = make_float4(0.f, 0.f, 0.f, 0.f);
    #pragma unroll
    for (int m = 0; m < 4; ++m) {
        const int r = bid + K1_BLOCKS * (sub + 8 * m);   // < 16384 always
        const float* src = (r < M_ROWS)
            ? (mashup + (size_t)r * DIM)
            : (new_api + (size_t)(r - M_ROWS) * DIM);
        const float4 x = reinterpret_cast<const float4*>(src)[c4];
        acc.x += x.x; acc.y += x.y; acc.z += x.z; acc.w += x.w;
    }

    __shared__ float4 sm[512];
    sm[t] = acc;
    __syncthreads();
    if (t < 64) {
        float4 r = sm[t];
        #pragma unroll
        for (int s = 1; s < 8; ++s) {
            const float4 a = sm[t + 64 * s];
            r.x += a.x; r.y += a.y; r.z += a.z; r.w += a.w;
        }
        reinterpret_cast<float4*>(g_part + (size_t)bid * DIM)[t] = r;
    }
}

// ---------------------------------------------------------------------------
// reduce1: collapse 512 partial rows -> 32. Block b reduces rows
// p = b + 32*(seg + 4*m), seg = t>>6, m = 0..3 (all L2-resident, 16KB/block).
// ---------------------------------------------------------------------------
__global__ void __launch_bounds__(256, 4)
reduce1_kernel() {
    const int t   = threadIdx.x;
    const int c4  = t & 63;
    const int seg = t >> 6;                 // 0..3
    const int b   = blockIdx.x;

    float4 acc = make_float4(0.f, 0.f, 0.f, 0.f);
    #pragma unroll
    for (int m = 0; m < 4; ++m) {
        const int p = b + R1_BLOCKS * (seg + 4 * m);     // < 512
        const float4 x = reinterpret_cast<const float4*>(
            g_part + (size_t)p * DIM)[c4];
        acc.x += x.x; acc.y += x.y; acc.z += x.z; acc.w += x.w;
    }

    __shared__ float4 sm[256];
    sm[t] = acc;
    __syncthreads();
    if (t < 64) {
        const float4 a = sm[t], bb = sm[t + 64],
                     c = sm[t + 128], d = sm[t + 192];
        reinterpret_cast<float4*>(g_part2 + (size_t)b * DIM)[t] =
            make_float4(a.x + bb.x + c.x + d.x, a.y + bb.y + c.y + d.y,
                        a.z + bb.z + c.z + d.z, a.w + bb.w + c.w + d.w);
    }
}

// ---------------------------------------------------------------------------
// k2a: 64 blocks x 256 threads. Each block re-reduces the 32 stage-2
// partials into s[256] (32KB L2-hot), then computes its 4 columns of
// ksum[j] = sum_i s[i]*k_w[i][j] + N*k_b[j].
// ---------------------------------------------------------------------------
__global__ void __launch_bounds__(256, 1)
ksum_kernel(const float* __restrict__ k_w,
            const float* __restrict__ k_b) {
    __shared__ float4 red[256];
    __shared__ float  s[DIM];

    const int t   = threadIdx.x;
    const int c4  = t & 63;
    const int seg = t >> 6;                 // 0..3

    float4 acc = make_float4(0.f, 0.f, 0.f, 0.f);
    #pragma unroll
    for (int m = 0; m < 8; ++m) {
        const int p = seg + 4 * m;          // 0..31
        const float4 x = reinterpret_cast<const float4*>(
            g_part2 + (size_t)p * DIM)[c4];
        acc.x += x.x; acc.y += x.y; acc.z += x.z; acc.w += x.w;
    }
    red[t] = acc;
    __syncthreads();
    if (t < 64) {
        const float4 a = red[t], b = red[t + 64],
                     c = red[t + 128], d = red[t + 192];
        reinterpret_cast<float4*>(s)[t] = make_float4(
            a.x + b.x + c.x + d.x, a.y + b.y + c.y + d.y,
            a.z + b.z + c.z + d.z, a.w + b.w + c.w + d.w);
    }
    __syncthreads();

    // --- this block's 4 columns of ksum ---
    const int jb = blockIdx.x * 4;
    const float si = s[t];
    const float4 w = reinterpret_cast<const float4*>(
        k_w + (size_t)t * DIM + jb)[0];
    red[t] = make_float4(si * w.x, si * w.y, si * w.z, si * w.w);
    __syncthreads();
    #pragma unroll
    for (int off = 128; off >= 1; off >>= 1) {
        if (t < off) {
            const float4 a = red[t], b = red[t + off];
            red[t] = make_float4(a.x + b.x, a.y + b.y, a.z + b.z, a.w + b.w);
        }
        __syncthreads();
    }
    if (t == 0) {
        const float4 kb = reinterpret_cast<const float4*>(k_b + jb)[0];
        float4 r = red[0];
        r.x += (float)N_TOTAL * kb.x;
        r.y += (float)N_TOTAL * kb.y;
        r.z += (float)N_TOTAL * kb.z;
        r.w += (float)N_TOTAL * kb.w;
        reinterpret_cast<float4*>(g_ksum + jb)[0] = r;
    }
}

// ---------------------------------------------------------------------------
// k2b: 64 blocks x 256 threads. Block b computes v rows 4b..4b+3
// (v = q_w @ ksum). Block 0 also computes c = q_b . ksum.
// ---------------------------------------------------------------------------
__global__ void __launch_bounds__(256, 1)
vrow_kernel(const float* __restrict__ q_w,
            const float* __restrict__ q_b) {
    __shared__ float ks[DIM];
    __shared__ float red[256];

    const int t = threadIdx.x;
    ks[t] = g_ksum[t];
    __syncthreads();

    const int row = blockIdx.x * 4 + (t >> 6);
    const int i4  = t & 63;
    const float4 a = reinterpret_cast<const float4*>(
        q_w + (size_t)row * DIM)[i4];
    const float4 k = reinterpret_cast<const float4*>(ks)[i4];
    red[t] = a.x * k.x + a.y * k.y + a.z * k.z + a.w * k.w;
    __syncthreads();
    #pragma unroll
    for (int off = 32; off >= 1; off >>= 1) {
        if ((t & 63) < off) red[t] += red[t + off];
        __syncthreads();
    }
    if ((t & 63) == 0) g_v[row] = red[t];

    if (blockIdx.x == 0) {
        __syncthreads();
        red[t] = q_b[t] * ks[t];
        __syncthreads();
        #pragma unroll
        for (int off = 128; off >= 1; off >>= 1) {
            if (t < off) red[t] += red[t + off];
            __syncthreads();
        }
        if (t == 0) g_c = red[0];
    }
}

// ---------------------------------------------------------------------------
// k3: out[i] = (combine[i] . v + c) / 16,  combine = [mashup ; api]
// 512 blocks x 512 threads (16 warps), 2 rows per warp -> 32 rows/block,
// 4 independent float4 loads per thread. Single full-occupancy wave.
// Rows of one warp never straddle the 4096 boundary (row0 even).
// ---------------------------------------------------------------------------
__global__ void __launch_bounds__(512, 4)
final_kernel(const float* __restrict__ mashup,
             const float* __restrict__ api,
             float* __restrict__ out) {
    __shared__ float vs[DIM];
    __shared__ float sc;
    const int t = threadIdx.x;
    if (t < DIM) vs[t] = g_v[t];
    if (t == 0)  sc = g_c;
    __syncthreads();

    const int warp = t >> 5, lane = t & 31;
    const int row0 = (blockIdx.x * 16 + warp) * 2;   // 2 rows per warp

    const float* src;
    int base;
    if (row0 < M_ROWS) { src = mashup; base = row0; }
    else               { src = api;    base = row0 - M_ROWS; }

    const float4* vp = reinterpret_cast<const float4*>(vs);
    const float4 v0 = vp[lane], v1 = vp[lane + 32];

    const float4* p0 = reinterpret_cast<const float4*>(src + (size_t)base * DIM);
    const float4* p1 = reinterpret_cast<const float4*>(src + (size_t)(base + 1) * DIM);
    const float4 a0 = p0[lane], a1 = p0[lane + 32];
    const float4 b0 = p1[lane], b1 = p1[lane + 32];

    float accA = a0.x * v0.x + a0.y * v0.y + a0.z * v0.z + a0.w * v0.w
               + a1.x * v1.x + a1.y * v1.y + a1.z * v1.z + a1.w * v1.w;
    float accB = b0.x * v0.x + b0.y * v0.y + b0.z * v0.z + b0.w * v0.w
               + b1.x * v1.x + b1.y * v1.y + b1.z * v1.z + b1.w * v1.w;

    #pragma unroll
    for (int off = 16; off > 0; off >>= 1) {
        accA += __shfl_xor_sync(0xFFFFFFFFu, accA, off);
        accB += __shfl_xor_sync(0xFFFFFFFFu, accB, off);
    }
    if (lane == 0) {
        out[row0]     = (accA + sc) * 0.0625f;   // 1/sqrt(256)
        out[row0 + 1] = (accB + sc) * 0.0625f;
    }
}

// ---------------------------------------------------------------------------
// Launch. Inputs (metadata order): mashup, api, new_api, q_w, q_b, k_w, k_b,
// embedding_dim (fixed 256, unused).
// ---------------------------------------------------------------------------
extern "C" void kernel_launch(void* const* d_in, const int* in_sizes, int n_in,
                              void* d_out, int out_size) {
    const float* mashup  = (const float*)d_in[0];
    const float* api     = (const float*)d_in[1];
    const float* new_api = (const float*)d_in[2];
    const float* q_w     = (const float*)d_in[3];
    const float* q_b     = (const float*)d_in[4];
    const float* k_w     = (const float*)d_in[5];
    const float* k_b     = (const float*)d_in[6];
    float* out = (float*)d_out;

    colsum_kernel <<<K1_BLOCKS, 512>>>(mashup, new_api);
    reduce1_kernel<<<R1_BLOCKS, 256>>>();
    ksum_kernel   <<<DIM / 4, 256>>>(k_w, k_b);
    vrow_kernel   <<<DIM / 4, 256>>>(q_w, q_b);
    final_kernel  <<<K1_BLOCKS, 512>>>(mashup, api, out);
}